// round 10
// baseline (speedup 1.0000x reference)
#include <cuda_runtime.h>
#include <math.h>
#include <float.h>

#define KDIM 7168
#define NEXP 256
#define NGRP 8
#define GSIZE 32
#define TOPKN 8
#define TOPG 4
#define TTOT 8192
#define BSZ 2
#define SEQ 4096

// Scratch (no cudaMalloc allowed)
__device__ float g_logits[(size_t)TTOT * NEXP];   // 8 MB
__device__ float g_counts[BSZ * NEXP];
__device__ float g_ssum[BSZ * NEXP];

// ---------------------------------------------------------------------------
// XLA-style logistic: sigmoid(x) = 0.5 + 0.5 * tanh_xla(0.5 * x).
// ---------------------------------------------------------------------------
__device__ __forceinline__ float xla_sigmoid(float x) {
    float t  = __fmul_rn(0.5f, x);
    float tc = fminf(fmaxf(t, -7.90531110763549805f), 7.90531110763549805f);
    float x2 = __fmul_rn(tc, tc);
    float p = -2.76076847742355e-16f;
    p = __fadd_rn(__fmul_rn(p, x2),  2.00018790482477e-13f);
    p = __fadd_rn(__fmul_rn(p, x2), -8.60467152213735e-11f);
    p = __fadd_rn(__fmul_rn(p, x2),  5.12229709037114e-08f);
    p = __fadd_rn(__fmul_rn(p, x2),  1.48572235717979e-05f);
    p = __fadd_rn(__fmul_rn(p, x2),  6.37261928875436e-04f);
    p = __fadd_rn(__fmul_rn(p, x2),  4.89352455891786e-03f);
    p = __fmul_rn(p, tc);
    float q = 1.19825839466702e-06f;
    q = __fadd_rn(__fmul_rn(q, x2), 1.18534705686654e-04f);
    q = __fadd_rn(__fmul_rn(q, x2), 2.26843463243900e-03f);
    q = __fadd_rn(__fmul_rn(q, x2), 4.89352518554385e-03f);
    float th = __fdiv_rn(p, q);
    th = (fabsf(t) < 0.0004f) ? t : th;
    return __fadd_rn(0.5f, __fmul_rn(0.5f, th));
}

__global__ void zero_kernel() {
    int i = threadIdx.x;
    if (i < BSZ * NEXP) { g_counts[i] = 0.0f; g_ssum[i] = 0.0f; }
}

// ---------------------------------------------------------------------------
// GEMM: logits[t][e] = sum_k x[t][k] * W[e][k]   (NT, both K-major)
// BM=128, BN=128, BK=8, 512 threads (4 warps/SMSP), 8x4 micro-tile.
// Each output keeps a strict ascending-k single-accumulator IEEE-FMA chain
// (bit-stable — identical rounding to previous passing rounds; do not alter
// the k-order or accumulator structure).
// ---------------------------------------------------------------------------
__global__ __launch_bounds__(512) void gemm_kernel(const float* __restrict__ A,
                                                   const float* __restrict__ B) {
    __shared__ float As[8][128];
    __shared__ float Bs[8][128];
    const int tid = threadIdx.x;
    const int tx = tid & 31;          // 0..31  -> e micro-col (x4)
    const int ty = tid >> 5;          // 0..15  -> t micro-row (x8)
    const int t0 = blockIdx.y * 128;
    const int e0 = blockIdx.x * 128;

    // Loader role: tid<256 loads A tile, tid>=256 loads B tile (1 float4 each)
    const int ldid = tid & 255;
    const int lr = ldid >> 1;         // 0..127
    const int lc = (ldid & 1) * 4;    // 0 or 4
    const bool isA = (tid < 256);
    const float* Gb = isA ? (A + (size_t)(t0 + lr) * KDIM)
                          : (B + (size_t)(e0 + lr) * KDIM);
    float* Sb = isA ? &As[0][0] : &Bs[0][0];

    float acc[8][4];
#pragma unroll
    for (int i = 0; i < 8; i++)
#pragma unroll
        for (int j = 0; j < 4; j++) acc[i][j] = 0.0f;

    float4 gv = *(const float4*)(Gb + lc);

    for (int k0 = 0; k0 < KDIM; k0 += 8) {
        __syncthreads();
        // store transposed: S[kc][row]
        Sb[(lc + 0) * 128 + lr] = gv.x;
        Sb[(lc + 1) * 128 + lr] = gv.y;
        Sb[(lc + 2) * 128 + lr] = gv.z;
        Sb[(lc + 3) * 128 + lr] = gv.w;
        __syncthreads();
        if (k0 + 8 < KDIM) gv = *(const float4*)(Gb + k0 + 8 + lc);

#pragma unroll
        for (int kk = 0; kk < 8; kk++) {
            float4 a0 = *(const float4*)&As[kk][ty * 8];      // broadcast
            float4 a1 = *(const float4*)&As[kk][ty * 8 + 4];  // broadcast
            float4 b0 = *(const float4*)&Bs[kk][tx * 4];      // conflict-free
            float a[8] = {a0.x, a0.y, a0.z, a0.w, a1.x, a1.y, a1.z, a1.w};
            float b[4] = {b0.x, b0.y, b0.z, b0.w};
#pragma unroll
            for (int i = 0; i < 8; i++)
#pragma unroll
                for (int j = 0; j < 4; j++)
                    acc[i][j] = __fmaf_rn(a[i], b[j], acc[i][j]);
        }
    }

#pragma unroll
    for (int i = 0; i < 8; i++) {
        int row = t0 + ty * 8 + i;
        float* Crow = g_logits + (size_t)row * NEXP + e0 + tx * 4;
        *(float4*)Crow = make_float4(acc[i][0], acc[i][1], acc[i][2], acc[i][3]);
    }
}

// ---------------------------------------------------------------------------
// Routing: one warp per token. Lane l owns experts {32j+l : j=0..7}.
// Top-8: warp-max score, then MIN INDEX among scores within a ~2-ulp window
// of the max (index-ascending on ulp-scale ties, matching jax.lax.top_k on
// the reference's rounded scores). DO NOT change the window semantics.
// ---------------------------------------------------------------------------
__global__ __launch_bounds__(256) void route_kernel(const float* __restrict__ bias,
                                                    float* __restrict__ out) {
    const unsigned FULL = 0xffffffffu;
    int warp = (blockIdx.x * blockDim.x + threadIdx.x) >> 5;
    int l = threadIdx.x & 31;
    if (warp >= TTOT) return;
    const int t = warp;
    const int b = t / SEQ;
    const float* lgp = g_logits + (size_t)t * NEXP;

    float orig[NGRP], val[NGRP], gscore[NGRP];
#pragma unroll
    for (int j = 0; j < NGRP; j++) {
        float xv = lgp[j * GSIZE + l];
        float s = xla_sigmoid(xv);
        orig[j] = s;
        val[j] = __fadd_rn(s, bias[j * GSIZE + l]);
    }

    // group scores: sum of top-2 (biased) per group
#pragma unroll
    for (int j = 0; j < NGRP; j++) {
        float m1 = val[j], m2 = -FLT_MAX;
#pragma unroll
        for (int off = 16; off > 0; off >>= 1) {
            float o1 = __shfl_xor_sync(FULL, m1, off);
            float o2 = __shfl_xor_sync(FULL, m2, off);
            float hi = fmaxf(m1, o1);
            float lo = fminf(m1, o1);
            m2 = fmaxf(fmaxf(m2, o2), lo);
            m1 = hi;
        }
        gscore[j] = __fadd_rn(m1, m2);
    }

    // top-4 groups (strict > => lowest index on ties)
    unsigned gsel = 0;
    for (int r = 0; r < TOPG; r++) {
        float best = -FLT_MAX; int bi = 0;
#pragma unroll
        for (int j = 0; j < NGRP; j++)
            if (!((gsel >> j) & 1u) && gscore[j] > best) { best = gscore[j]; bi = j; }
        gsel |= 1u << bi;
    }
#pragma unroll
    for (int j = 0; j < NGRP; j++)
        if (!((gsel >> j) & 1u)) val[j] = -FLT_MAX;   // exclude masked groups

    // top-8 experts with ulp-window tie handling
    float wsel[TOPKN]; int isel[TOPKN];
#pragma unroll
    for (int r = 0; r < TOPKN; r++) {
        float m = -FLT_MAX;
#pragma unroll
        for (int j = 0; j < NGRP; j++) m = fmaxf(m, val[j]);
#pragma unroll
        for (int off = 16; off > 0; off >>= 1)
            m = fmaxf(m, __shfl_xor_sync(FULL, m, off));
        float thr = m - fabsf(m) * 2.4e-7f;
        int cidx = 0x7fffffff;
#pragma unroll
        for (int j = 0; j < NGRP; j++)
            if (val[j] >= thr && cidx == 0x7fffffff) cidx = j * GSIZE + l;
#pragma unroll
        for (int off = 16; off > 0; off >>= 1)
            cidx = min(cidx, __shfl_xor_sync(FULL, cidx, off));
        int jw = cidx >> 5, lw = cidx & 31;
        float cand = 0.0f;
#pragma unroll
        for (int j = 0; j < NGRP; j++) if (j == jw) cand = orig[j];
        float w = __shfl_sync(FULL, cand, lw);
        if (l == lw) {
#pragma unroll
            for (int j = 0; j < NGRP; j++) if (j == jw) val[j] = -FLT_MAX;
        }
        wsel[r] = w;
        isel[r] = cidx;
    }

    float s = 0.0f;
#pragma unroll
    for (int r = 0; r < TOPKN; r++) s = __fadd_rn(s, wsel[r]);

    if (l == 0) {
        float* ow = out + (size_t)t * TOPKN;
        float* oi = out + (size_t)TTOT * TOPKN + (size_t)t * TOPKN;
#pragma unroll
        for (int r = 0; r < TOPKN; r++) {
            ow[r] = __fmul_rn(__fdiv_rn(wsel[r], s), 2.5f);
            oi[r] = (float)isel[r];
        }
#pragma unroll
        for (int r = 0; r < TOPKN; r++)
            atomicAdd(&g_counts[b * NEXP + isel[r]], 1.0f);
    }
}

// ---------------------------------------------------------------------------
// Per-(batch, expert) sum of sigmoid(logits) over the sequence.
// ---------------------------------------------------------------------------
__global__ __launch_bounds__(256) void ssum_kernel() {
    int row0 = blockIdx.x * 16;
    int b = row0 / SEQ;
    int e = threadIdx.x;
    float s = 0.0f;
#pragma unroll 8
    for (int r = 0; r < 16; r++) {
        float xv = g_logits[(size_t)(row0 + r) * NEXP + e];
        s += xla_sigmoid(xv);
    }
    atomicAdd(&g_ssum[b * NEXP + e], s);
}

__global__ void aux_kernel(float* __restrict__ out) {
    __shared__ float red[512];
    int i = threadIdx.x;  // 512 threads
    float term = (g_counts[i] * (1.0f / 128.0f)) * (g_ssum[i] * (1.0f / 4096.0f));
    red[i] = term;
    __syncthreads();
    for (int st = 256; st > 0; st >>= 1) {
        if (i < st) red[i] += red[i + st];
        __syncthreads();
    }
    if (i == 0) out[2 * TTOT * TOPKN] = red[0] * 0.5f * 0.001f;
}

extern "C" void kernel_launch(void* const* d_in, const int* in_sizes, int n_in,
                              void* d_out, int out_size) {
    const float* x    = (const float*)d_in[0];   // [2,4096,7168] fp32
    const float* w    = (const float*)d_in[1];   // [256,7168] fp32
    const float* bias = (const float*)d_in[2];   // [256] fp32
    float* out = (float*)d_out;                  // [T*8 weights | T*8 indices | aux]

    zero_kernel<<<1, 512>>>();
    dim3 ggrid(NEXP / 128, TTOT / 128);
    gemm_kernel<<<ggrid, 512>>>(x, w);
    route_kernel<<<TTOT / 8, 256>>>(bias, out);
    ssum_kernel<<<TTOT / 16, 256>>>();
    aux_kernel<<<1, 512>>>(out);
}